// round 4
// baseline (speedup 1.0000x reference)
#include <cuda_runtime.h>
#include <cstdint>

// Problem constants
#define BB   64      // batch
#define TT   512     // time
#define DD   512     // input dim
#define HH   512     // hidden dim
#define NG   2048    // 4*H gate columns
#define DH   1024    // D+H rows of W

// -------------------- scratch (device globals; no allocation) --------------------
// Zx[dir][t][b][4H] : precomputed x-part of gate preactivations (+bias)
__device__ float g_zx[(size_t)2 * TT * BB * NG];        // 536 MB
// h ping-pong: [buf][dir][b][H]
__device__ float g_h[2 * 2 * BB * HH];                  // 512 KB
__device__ unsigned int g_bar_count;

// -------------------- init: zero h, reset barrier (every replay) --------------------
__global__ void init_kernel() {
    int i = blockIdx.x * blockDim.x + threadIdx.x;
    if (i == 0) g_bar_count = 0u;
    if (i < 2 * 2 * BB * HH) g_h[i] = 0.0f;
}

// -------------------- kernel A: input projection GEMM --------------------
// C[m, n] = x[m, 0:512] @ W[0:512, n] + bias[n], stored as Zx[dir][t][b][n], m = b*T + t
#define BM 128
#define BN 128
#define BK 8
#define TM 8
#define TN 8

__global__ __launch_bounds__(256) void input_gemm(
    const float* __restrict__ x,
    const float* __restrict__ Wf, const float* __restrict__ bf,
    const float* __restrict__ Wb, const float* __restrict__ bb)
{
    const int dir = blockIdx.z;
    const float* __restrict__ W    = dir ? Wb : Wf;
    const float* __restrict__ bias = dir ? bb : bf;
    float* __restrict__ zx = g_zx + (size_t)dir * TT * BB * NG;

    __shared__ float As[BK][BM];
    __shared__ float Bs[BK][BN];

    const int m0 = blockIdx.y * BM;
    const int n0 = blockIdx.x * BN;
    const int tid = threadIdx.x;
    const int tx = tid & 15;       // 0..15 -> cols tx*8
    const int ty = tid >> 4;       // 0..15 -> rows ty*8

    const int arow = tid >> 1;             // 0..127
    const int ac4  = (tid & 1) * 4;        // 0 or 4
    const int brow = tid >> 5;             // 0..7
    const int bc4  = (tid & 31) * 4;       // 0..124

    float acc[TM][TN];
#pragma unroll
    for (int i = 0; i < TM; i++)
#pragma unroll
        for (int j = 0; j < TN; j++) acc[i][j] = 0.0f;

    for (int kk = 0; kk < DD; kk += BK) {
        float4 av = *(const float4*)&x[(size_t)(m0 + arow) * DD + kk + ac4];
        float4 bv = *(const float4*)&W[(size_t)(kk + brow) * NG + n0 + bc4];
        __syncthreads();   // previous tile fully consumed
        As[ac4 + 0][arow] = av.x;
        As[ac4 + 1][arow] = av.y;
        As[ac4 + 2][arow] = av.z;
        As[ac4 + 3][arow] = av.w;
        *(float4*)&Bs[brow][bc4] = bv;
        __syncthreads();
#pragma unroll
        for (int k = 0; k < BK; k++) {
            float a[TM], b[TN];
#pragma unroll
            for (int i = 0; i < TM; i++) a[i] = As[k][ty * TM + i];
#pragma unroll
            for (int j = 0; j < TN; j++) b[j] = Bs[k][tx * TN + j];
#pragma unroll
            for (int i = 0; i < TM; i++)
#pragma unroll
                for (int j = 0; j < TN; j++) acc[i][j] = fmaf(a[i], b[j], acc[i][j]);
        }
    }

    // epilogue: m = b*T + t ; Zx layout [t][b][n]
#pragma unroll
    for (int i = 0; i < TM; i++) {
        int m = m0 + ty * TM + i;
        int b = m >> 9;           // /512
        int t = m & 511;
        float* zrow = zx + ((size_t)t * BB + b) * NG;
#pragma unroll
        for (int j = 0; j < TN; j++) {
            int n = n0 + tx * TN + j;
            zrow[n] = acc[i][j] + bias[n];
        }
    }
}

// -------------------- kernel B: persistent recurrent scan --------------------
// 256 CTAs = 2 dirs x 128 blocks; block owns 4 hidden units (16 z-columns).
// Per step: z = h_prev @ Wh_slice + Zx ; gates; h,c update; grid barrier.

__device__ __forceinline__ float sigm(float v) { return 1.0f / (1.0f + expf(-v)); }

__global__ void __launch_bounds__(256, 2) lstm_scan(
    const float* __restrict__ Wf, const float* __restrict__ Wb,
    float* __restrict__ out)
{
    const int dir = blockIdx.x >> 7;     // 0 fw, 1 bw
    const int blk = blockIdx.x & 127;
    const int hu0 = blk * 4;             // first of 4 hidden units
    const int tid = threadIdx.x;

    __shared__ float W_s[16][516];       // [lc][k], padded (2-way max)
    __shared__ float Hs[64][32];         // h chunk [b][k]
    __shared__ float Zs[64][17];         // gate exchange, padded

    const float* __restrict__ W = dir ? Wb : Wf;

    // load W slice: rows 512..1023 (h part), cols {g*512 + hu0 + u}, lc = g*4+u
    for (int i = tid; i < 16 * HH; i += 256) {
        int k  = i >> 4;
        int lc = i & 15;
        int col = (lc >> 2) * HH + hu0 + (lc & 3);
        W_s[lc][k] = W[(size_t)(DD + k) * NG + col];
    }
    __syncthreads();

    const float* __restrict__ zxd = g_zx + (size_t)dir * TT * BB * NG;

    // GEMM-phase thread mapping
    const int lc = tid & 15;
    const int bq = tid >> 4;                              // 0..15
    const int colg = (lc >> 2) * HH + hu0 + (lc & 3);     // global z column
    // gate-phase thread mapping
    const int gb = tid >> 2;                              // batch 0..63
    const int gu = tid & 3;                               // hidden unit within block

    // h staging indices (512 float4 per chunk, 2 per thread)
    const int f0 = tid, f1 = tid + 256;
    const int r0 = f0 >> 3, c0 = (f0 & 7) << 2;
    const int r1 = f1 >> 3, c1 = (f1 & 7) << 2;

    float c_st = 0.0f;                                    // cell state for (gb, gu)
    unsigned bar_target = 0;

    for (int s = 0; s < TT; s++) {
        const int t = dir ? (TT - 1 - s) : s;
        const float* __restrict__ hin = g_h + (((s & 1) * 2 + dir) << 15); // *BB*HH (32768)

        float acc0 = 0.f, acc1 = 0.f, acc2 = 0.f, acc3 = 0.f;

        // prefetch chunk 0
        float4 v0 = __ldcg((const float4*)(hin + r0 * HH + c0));
        float4 v1 = __ldcg((const float4*)(hin + r1 * HH + c1));

        for (int kk = 0; kk < HH; kk += 32) {
            __syncthreads();                  // previous Hs consumed (and Zs from prev step)
            *(float4*)&Hs[r0][c0] = v0;
            *(float4*)&Hs[r1][c1] = v1;
            __syncthreads();

            if (kk + 32 < HH) {               // prefetch next chunk, hidden under compute
                v0 = __ldcg((const float4*)(hin + r0 * HH + kk + 32 + c0));
                v1 = __ldcg((const float4*)(hin + r1 * HH + kk + 32 + c1));
            }

#pragma unroll
            for (int k4 = 0; k4 < 32; k4 += 4) {
                float4 w  = *(const float4*)&W_s[lc][kk + k4];
                float4 h0 = *(const float4*)&Hs[bq     ][k4];
                float4 h1 = *(const float4*)&Hs[bq + 16][k4];
                float4 h2 = *(const float4*)&Hs[bq + 32][k4];
                float4 h3 = *(const float4*)&Hs[bq + 48][k4];
                acc0 = fmaf(w.x, h0.x, acc0); acc0 = fmaf(w.y, h0.y, acc0);
                acc0 = fmaf(w.z, h0.z, acc0); acc0 = fmaf(w.w, h0.w, acc0);
                acc1 = fmaf(w.x, h1.x, acc1); acc1 = fmaf(w.y, h1.y, acc1);
                acc1 = fmaf(w.z, h1.z, acc1); acc1 = fmaf(w.w, h1.w, acc1);
                acc2 = fmaf(w.x, h2.x, acc2); acc2 = fmaf(w.y, h2.y, acc2);
                acc2 = fmaf(w.z, h2.z, acc2); acc2 = fmaf(w.w, h2.w, acc2);
                acc3 = fmaf(w.x, h3.x, acc3); acc3 = fmaf(w.y, h3.y, acc3);
                acc3 = fmaf(w.z, h3.z, acc3); acc3 = fmaf(w.w, h3.w, acc3);
            }
        }

        // add precomputed x-part (+bias), exchange gates through SMEM
        {
            const float* zrow = zxd + (size_t)t * BB * NG;
            Zs[bq     ][lc] = acc0 + zrow[(size_t)(bq     ) * NG + colg];
            Zs[bq + 16][lc] = acc1 + zrow[(size_t)(bq + 16) * NG + colg];
            Zs[bq + 32][lc] = acc2 + zrow[(size_t)(bq + 32) * NG + colg];
            Zs[bq + 48][lc] = acc3 + zrow[(size_t)(bq + 48) * NG + colg];
        }
        __syncthreads();

        {
            float zi = Zs[gb][     gu];
            float zj = Zs[gb][ 4 + gu];
            float zf = Zs[gb][ 8 + gu];
            float zo = Zs[gb][12 + gu];
            c_st = sigm(zf + 1.0f) * c_st + sigm(zi) * tanhf(zj);
            float h = sigm(zo) * tanhf(c_st);

            float* hout = g_h + (((((s + 1) & 1) * 2) + dir) << 15);
            hout[gb * HH + hu0 + gu] = h;
            out[((size_t)gb * TT + t) * (2 * HH) + (dir << 9) + hu0 + gu] = h;
        }

        // ---- grid barrier (monotonic counter, one per step) ----
        __threadfence();
        __syncthreads();
        bar_target += gridDim.x;
        if (tid == 0) {
            atomicAdd(&g_bar_count, 1u);
            while (*(volatile unsigned int*)&g_bar_count < bar_target) {
                __nanosleep(64);
            }
        }
        __syncthreads();
        __threadfence();
    }
}

// -------------------- launch --------------------
extern "C" void kernel_launch(void* const* d_in, const int* in_sizes, int n_in,
                              void* d_out, int out_size) {
    const float* x  = (const float*)d_in[0];
    const float* Wf = (const float*)d_in[1];
    const float* bf = (const float*)d_in[2];
    const float* Wb = (const float*)d_in[3];
    const float* bb = (const float*)d_in[4];
    float* out = (float*)d_out;

    init_kernel<<<512, 256>>>();

    dim3 g(NG / BN, (BB * TT) / BM, 2);     // (16, 256, 2)
    input_gemm<<<g, 256>>>(x, Wf, bf, Wb, bb);

    lstm_scan<<<256, 256>>>(Wf, Wb, out);
}

// round 17
// speedup vs baseline: 1.1145x; 1.1145x over previous
#include <cuda_runtime.h>
#include <cuda_bf16.h>
#include <cstdint>

// Problem constants
#define BB   64      // batch
#define TT   512     // time
#define DD   512     // input dim
#define HH   512     // hidden dim
#define NG   2048    // 4*H gate columns
#define MTOT (BB*TT) // 32768 rows of the input GEMM

// -------------------- scratch (device globals; no allocation) --------------------
__device__ float g_zx[(size_t)2 * TT * BB * NG];                 // 536 MB
__device__ float g_h[2 * 2 * BB * HH];                           // 512 KB
__device__ unsigned int g_bar_count;
// split-bf16 operands for tensor-core input GEMM
__device__ __align__(16) __nv_bfloat16 g_xhi[(size_t)MTOT * DD]; // 33.5 MB
__device__ __align__(16) __nv_bfloat16 g_xlo[(size_t)MTOT * DD];
__device__ __align__(16) __nv_bfloat16 g_wthi[(size_t)2 * NG * DD]; // [dir][n][k] 4 MB
__device__ __align__(16) __nv_bfloat16 g_wtlo[(size_t)2 * NG * DD];

// -------------------- helpers --------------------
__device__ __forceinline__ uint32_t smem_u32(const void* p) {
    uint32_t a;
    asm("{ .reg .u64 t; cvta.to.shared.u64 t, %1; cvt.u32.u64 %0, t; }" : "=r"(a) : "l"(p));
    return a;
}

// m16n8k16 bf16 mma, fp32 accum (base ISA, sm_80+)
__device__ __forceinline__ void mma16816(float* c, const uint32_t* a, const uint32_t* b) {
    asm volatile("mma.sync.aligned.m16n8k16.row.col.f32.bf16.bf16.f32 "
        "{%0,%1,%2,%3}, {%4,%5,%6,%7}, {%8,%9}, {%0,%1,%2,%3};"
        : "+f"(c[0]), "+f"(c[1]), "+f"(c[2]), "+f"(c[3])
        : "r"(a[0]), "r"(a[1]), "r"(a[2]), "r"(a[3]), "r"(b[0]), "r"(b[1]));
}

#define PADK 40   // bf16 elems per padded smem row (80 B): conflict-free ldmatrix phases

// A fragment: 16x16 row-major at (row0, col0); regs a0..a3 = (m0-7,k0-7),(m8-15,k0-7),(m0-7,k8-15),(m8-15,k8-15)
__device__ __forceinline__ void lda_frag(uint32_t* a, const __nv_bfloat16* base,
                                         int row0, int col0, int lane) {
    int mat = lane >> 3, ri = lane & 7;
    int r = row0 + (mat & 1) * 8 + ri;
    int c = col0 + (mat >> 1) * 8;
    uint32_t addr = smem_u32(base + r * PADK + c);
    asm volatile("ldmatrix.sync.aligned.m8n8.x4.shared.b16 {%0,%1,%2,%3}, [%4];"
        : "=r"(a[0]), "=r"(a[1]), "=r"(a[2]), "=r"(a[3]) : "r"(addr));
}

// B fragments from [n][k] storage (k contiguous == col-major KxN): NON-trans ldmatrix.
// Covers 16 n-rows x 16 k at (nrow0, col0).
// regs: b[0]=(k0-7,n0-7), b[1]=(k8-15,n0-7), b[2]=(k0-7,n8-15), b[3]=(k8-15,n8-15)
__device__ __forceinline__ void ldb_frag(uint32_t* b, const __nv_bfloat16* base,
                                         int nrow0, int col0, int lane) {
    int mat = lane >> 3, ri = lane & 7;
    int r = nrow0 + (mat >> 1) * 8 + ri;
    int c = col0 + (mat & 1) * 8;
    uint32_t addr = smem_u32(base + r * PADK + c);
    asm volatile("ldmatrix.sync.aligned.m8n8.x4.shared.b16 {%0,%1,%2,%3}, [%4];"
        : "=r"(b[0]), "=r"(b[1]), "=r"(b[2]), "=r"(b[3]) : "r"(addr));
}

// -------------------- init: zero h, reset barrier (every replay) --------------------
__global__ void init_kernel() {
    int i = blockIdx.x * blockDim.x + threadIdx.x;
    if (i == 0) g_bar_count = 0u;
    if (i < 2 * 2 * BB * HH) g_h[i] = 0.0f;
}

// -------------------- split-bf16 conversion kernels --------------------
__global__ void conv_x(const float* __restrict__ x) {
    size_t i = (size_t)blockIdx.x * blockDim.x + threadIdx.x;
    if (i < (size_t)MTOT * DD) {
        float v = x[i];
        __nv_bfloat16 h = __float2bfloat16(v);
        g_xhi[i] = h;
        g_xlo[i] = __float2bfloat16(v - __bfloat162float(h));
    }
}

__global__ void conv_w(const float* __restrict__ Wf, const float* __restrict__ Wb) {
    size_t i = (size_t)blockIdx.x * blockDim.x + threadIdx.x;
    if (i < (size_t)2 * DD * NG) {
        int dir = (int)(i / ((size_t)DD * NG));
        int r   = (int)(i % ((size_t)DD * NG));
        int k = r / NG, n = r % NG;
        float v = (dir ? Wb : Wf)[(size_t)k * NG + n];
        __nv_bfloat16 h = __float2bfloat16(v);
        size_t o = (size_t)dir * NG * DD + (size_t)n * DD + k;
        g_wthi[o] = h;
        g_wtlo[o] = __float2bfloat16(v - __bfloat162float(h));
    }
}

// -------------------- kernel A: mma.sync split-bf16 input GEMM --------------------
// Z[m,n] = sum_k (xhi+xlo)[m,k]*(whi+wlo)[n,k] (lo*lo dropped), + bias.
// Block 128x128, 8 warps (warp tile 64x32), K-chunks of 32.
__global__ void __launch_bounds__(256) mma_input_gemm(
    const float* __restrict__ bf_, const float* __restrict__ bb_)
{
    __shared__ __nv_bfloat16 sAh[128 * PADK];
    __shared__ __nv_bfloat16 sAl[128 * PADK];
    __shared__ __nv_bfloat16 sBh[128 * PADK];
    __shared__ __nv_bfloat16 sBl[128 * PADK];

    const int tid = threadIdx.x, wid = tid >> 5, lane = tid & 31;
    const int wm = wid >> 2, wn = wid & 3;          // warp grid 2 x 4
    const int n0 = blockIdx.x * 128;
    const int m0 = blockIdx.y * 128;
    const int dir = blockIdx.z;

    const __nv_bfloat16* __restrict__ xh = g_xhi;
    const __nv_bfloat16* __restrict__ xl = g_xlo;
    const __nv_bfloat16* __restrict__ wh = g_wthi + (size_t)dir * NG * DD;
    const __nv_bfloat16* __restrict__ wl = g_wtlo + (size_t)dir * NG * DD;
    const float* __restrict__ bias = dir ? bb_ : bf_;

    float acc[4][4][4];
#pragma unroll
    for (int i = 0; i < 4; i++)
#pragma unroll
        for (int j = 0; j < 4; j++)
#pragma unroll
            for (int q = 0; q < 4; q++) acc[i][j][q] = 0.0f;

    for (int c = 0; c < 16; c++) {
        const int kk = c * 32;
        __syncthreads();                 // previous tiles fully consumed
#pragma unroll
        for (int j = 0; j < 8; j++) {
            int u = tid + j * 256;       // 0..2047
            int mtx = u >> 9;            // 0..3: Ah, Al, Bh, Bl
            int v = u & 511;
            int r = v >> 2, q = v & 3;   // row 0..127, 16B quad 0..3
            uint32_t soff = (uint32_t)(r * PADK + q * 8);   // in bf16 elems
            if (mtx == 0) {
                *(uint4*)(sAh + soff) = *(const uint4*)(xh + (size_t)(m0 + r) * DD + kk + q * 8);
            } else if (mtx == 1) {
                *(uint4*)(sAl + soff) = *(const uint4*)(xl + (size_t)(m0 + r) * DD + kk + q * 8);
            } else if (mtx == 2) {
                *(uint4*)(sBh + soff) = *(const uint4*)(wh + (size_t)(n0 + r) * DD + kk + q * 8);
            } else {
                *(uint4*)(sBl + soff) = *(const uint4*)(wl + (size_t)(n0 + r) * DD + kk + q * 8);
            }
        }
        __syncthreads();

#pragma unroll
        for (int ks = 0; ks < 32; ks += 16) {
            uint32_t Bh2[2][4], Bl2[2][4];
            ldb_frag(Bh2[0], sBh, wn * 32 +  0, ks, lane);
            ldb_frag(Bh2[1], sBh, wn * 32 + 16, ks, lane);
            ldb_frag(Bl2[0], sBl, wn * 32 +  0, ks, lane);
            ldb_frag(Bl2[1], sBl, wn * 32 + 16, ks, lane);
#pragma unroll
            for (int mf = 0; mf < 4; mf++) {
                uint32_t A1[4];
                lda_frag(A1, sAh, wm * 64 + mf * 16, ks, lane);
#pragma unroll
                for (int g = 0; g < 4; g++) {
                    mma16816(acc[mf][g], A1, &Bh2[g >> 1][(g & 1) * 2]);  // hi*hi
                    mma16816(acc[mf][g], A1, &Bl2[g >> 1][(g & 1) * 2]);  // hi*lo
                }
                lda_frag(A1, sAl, wm * 64 + mf * 16, ks, lane);
#pragma unroll
                for (int g = 0; g < 4; g++) {
                    mma16816(acc[mf][g], A1, &Bh2[g >> 1][(g & 1) * 2]);  // lo*hi
                }
            }
        }
    }

    // epilogue: C frag rows lane>>2 (+8), cols (lane&3)*2 (+1)
    const int r0 = lane >> 2;
    const int cb = (lane & 3) * 2;
    float* __restrict__ zxd = g_zx + (size_t)dir * TT * BB * NG;
#pragma unroll
    for (int mf = 0; mf < 4; mf++) {
#pragma unroll
        for (int half = 0; half < 2; half++) {
            int m = m0 + wm * 64 + mf * 16 + half * 8 + r0;
            int b = m >> 9;           // /512
            int t = m & 511;
            float* zrow = zxd + ((size_t)t * BB + b) * NG;
#pragma unroll
            for (int g = 0; g < 4; g++) {
                int n = n0 + wn * 32 + g * 8 + cb;
                float2 v;
                v.x = acc[mf][g][half * 2 + 0] + bias[n];
                v.y = acc[mf][g][half * 2 + 1] + bias[n + 1];
                *(float2*)&zrow[n] = v;
            }
        }
    }
}

// -------------------- kernel B: persistent recurrent scan (unchanged) --------------------
__device__ __forceinline__ float sigm(float v) { return 1.0f / (1.0f + expf(-v)); }

__global__ void __launch_bounds__(256, 2) lstm_scan(
    const float* __restrict__ Wf, const float* __restrict__ Wb,
    float* __restrict__ out)
{
    const int dir = blockIdx.x >> 7;
    const int blk = blockIdx.x & 127;
    const int hu0 = blk * 4;
    const int tid = threadIdx.x;

    __shared__ float W_s[16][516];
    __shared__ float Hs[64][32];
    __shared__ float Zs[64][17];

    const float* __restrict__ W = dir ? Wb : Wf;

    for (int i = tid; i < 16 * HH; i += 256) {
        int k  = i >> 4;
        int lc = i & 15;
        int col = (lc >> 2) * HH + hu0 + (lc & 3);
        W_s[lc][k] = W[(size_t)(DD + k) * NG + col];
    }
    __syncthreads();

    const float* __restrict__ zxd = g_zx + (size_t)dir * TT * BB * NG;

    const int lc = tid & 15;
    const int bq = tid >> 4;
    const int colg = (lc >> 2) * HH + hu0 + (lc & 3);
    const int gb = tid >> 2;
    const int gu = tid & 3;

    const int f0 = tid, f1 = tid + 256;
    const int r0 = f0 >> 3, c0 = (f0 & 7) << 2;
    const int r1 = f1 >> 3, c1 = (f1 & 7) << 2;

    float c_st = 0.0f;
    unsigned bar_target = 0;

    for (int s = 0; s < TT; s++) {
        const int t = dir ? (TT - 1 - s) : s;
        const float* __restrict__ hin = g_h + (((s & 1) * 2 + dir) << 15);

        float acc0 = 0.f, acc1 = 0.f, acc2 = 0.f, acc3 = 0.f;

        float4 v0 = __ldcg((const float4*)(hin + r0 * HH + c0));
        float4 v1 = __ldcg((const float4*)(hin + r1 * HH + c1));

        for (int kk = 0; kk < HH; kk += 32) {
            __syncthreads();
            *(float4*)&Hs[r0][c0] = v0;
            *(float4*)&Hs[r1][c1] = v1;
            __syncthreads();

            if (kk + 32 < HH) {
                v0 = __ldcg((const float4*)(hin + r0 * HH + kk + 32 + c0));
                v1 = __ldcg((const float4*)(hin + r1 * HH + kk + 32 + c1));
            }

#pragma unroll
            for (int k4 = 0; k4 < 32; k4 += 4) {
                float4 w  = *(const float4*)&W_s[lc][kk + k4];
                float4 h0 = *(const float4*)&Hs[bq     ][k4];
                float4 h1 = *(const float4*)&Hs[bq + 16][k4];
                float4 h2 = *(const float4*)&Hs[bq + 32][k4];
                float4 h3 = *(const float4*)&Hs[bq + 48][k4];
                acc0 = fmaf(w.x, h0.x, acc0); acc0 = fmaf(w.y, h0.y, acc0);
                acc0 = fmaf(w.z, h0.z, acc0); acc0 = fmaf(w.w, h0.w, acc0);
                acc1 = fmaf(w.x, h1.x, acc1); acc1 = fmaf(w.y, h1.y, acc1);
                acc1 = fmaf(w.z, h1.z, acc1); acc1 = fmaf(w.w, h1.w, acc1);
                acc2 = fmaf(w.x, h2.x, acc2); acc2 = fmaf(w.y, h2.y, acc2);
                acc2 = fmaf(w.z, h2.z, acc2); acc2 = fmaf(w.w, h2.w, acc2);
                acc3 = fmaf(w.x, h3.x, acc3); acc3 = fmaf(w.y, h3.y, acc3);
                acc3 = fmaf(w.z, h3.z, acc3); acc3 = fmaf(w.w, h3.w, acc3);
            }
        }

        {
            const float* zrow = zxd + (size_t)t * BB * NG;
            Zs[bq     ][lc] = acc0 + zrow[(size_t)(bq     ) * NG + colg];
            Zs[bq + 16][lc] = acc1 + zrow[(size_t)(bq + 16) * NG + colg];
            Zs[bq + 32][lc] = acc2 + zrow[(size_t)(bq + 32) * NG + colg];
            Zs[bq + 48][lc] = acc3 + zrow[(size_t)(bq + 48) * NG + colg];
        }
        __syncthreads();

        {
            float zi = Zs[gb][     gu];
            float zj = Zs[gb][ 4 + gu];
            float zf = Zs[gb][ 8 + gu];
            float zo = Zs[gb][12 + gu];
            c_st = sigm(zf + 1.0f) * c_st + sigm(zi) * tanhf(zj);
            float h = sigm(zo) * tanhf(c_st);

            float* hout = g_h + (((((s + 1) & 1) * 2) + dir) << 15);
            hout[gb * HH + hu0 + gu] = h;
            out[((size_t)gb * TT + t) * (2 * HH) + (dir << 9) + hu0 + gu] = h;
        }

        __threadfence();
        __syncthreads();
        bar_target += gridDim.x;
        if (tid == 0) {
            atomicAdd(&g_bar_count, 1u);
            while (*(volatile unsigned int*)&g_bar_count < bar_target) {
                __nanosleep(64);
            }
        }
        __syncthreads();
        __threadfence();
    }
}

// -------------------- launch --------------------
extern "C" void kernel_launch(void* const* d_in, const int* in_sizes, int n_in,
                              void* d_out, int out_size) {
    const float* x  = (const float*)d_in[0];
    const float* Wf = (const float*)d_in[1];
    const float* bf = (const float*)d_in[2];
    const float* Wb = (const float*)d_in[3];
    const float* bb = (const float*)d_in[4];
    float* out = (float*)d_out;

    init_kernel<<<512, 256>>>();

    conv_x<<<((size_t)MTOT * DD + 255) / 256, 256>>>(x);
    conv_w<<<((size_t)2 * DD * NG + 255) / 256, 256>>>(Wf, Wb);

    mma_input_gemm<<<dim3(16, 256, 2), 256>>>(bf, bb);

    lstm_scan<<<256, 256>>>(Wf, Wb, out);
}